// round 6
// baseline (speedup 1.0000x reference)
#include <cuda_runtime.h>
#include <math.h>
#include <stddef.h>

#define B 32
#define H 512
#define V 32000
#define T 64
#define VB 128
#define NB 250            /* V / VB */
#define START_INDEX 1
#define XPAD 516          /* float pad: conflict-free float4 smem reads, lane = batch */

/* ------------------------- persistent device scratch ---------------------- */
__device__ float g_h0[2][B * H];
__device__ float g_c0[B * H];
__device__ float g_h1[2][B * H];
__device__ float g_c1[B * H];
__device__ float g_pre0[2048 * B];    /* ctx part of layer0 gates + b_ih + b_hh */
__device__ float g_pmax[NB * B];
__device__ float g_psum[NB * B];
__device__ int   g_pidx[NB * B];
__device__ float g_lse[T * B];

__device__ __forceinline__ float sigf(float x) { return 1.0f / (1.0f + expf(-x)); }

/* ---------------------------------------------------------------------------
 * k_pre: blocks [0,256): pre0[r][b] = W_ih_l0[r][512+ :] . ctx[b] + b_ih + b_hh
 *        blocks [256,264): zero all states.
 * ------------------------------------------------------------------------- */
__global__ __launch_bounds__(256) void k_pre(const float* __restrict__ ctx,
                                             const float* __restrict__ Wih0,
                                             const float* __restrict__ bih0,
                                             const float* __restrict__ bhh0) {
    int blk = blockIdx.x, tid = threadIdx.x;
    if (blk >= 256) {
        int g = (blk - 256) * 256 + tid;          /* 2048 threads total */
        for (int i = g; i < B * H; i += 2048) {
            g_h0[0][i] = 0.0f; g_h0[1][i] = 0.0f; g_c0[i] = 0.0f;
            g_h1[0][i] = 0.0f; g_h1[1][i] = 0.0f; g_c1[i] = 0.0f;
        }
        return;
    }
    extern __shared__ float smem[];
    float* s_x = smem;                            /* [32][XPAD] */
    for (int i = tid; i < B * 512; i += 256) {
        int b = i >> 9, k = i & 511;
        s_x[b * XPAD + k] = ctx[i];
    }
    __syncthreads();
    int w = tid >> 5, lane = tid & 31;
    int r = blk * 8 + w;
    const float4* wp = (const float4*)(Wih0 + (size_t)r * 1024 + 512);
    const float4* xp = (const float4*)(s_x + lane * XPAD);
    float a0 = 0.0f, a1 = 0.0f;
#pragma unroll 4
    for (int q = 0; q < 128; q++) {
        float4 a = wp[q], x = xp[q];
        a0 += a.x * x.x + a.z * x.z;
        a1 += a.y * x.y + a.w * x.w;
    }
    g_pre0[r * 32 + lane] = (a0 + a1) + bih0[r] + bhh0[r];
}

/* ---------------------------------------------------------------------------
 * k_lstm0: prologue = argmax/LSE reduction of step t-1 partials (redundant per
 * block; block 0 writes lse[t-1]); then layer-0 LSTM for 4 hidden units.
 * Grid 128 x 256. Warp w: gate rq = w>>1, k-half kh = w&1, 4 rows (jj 0..3).
 * ------------------------------------------------------------------------- */
__global__ __launch_bounds__(256) void k_lstm0(int t,
                                               const float* __restrict__ emb,
                                               const float* __restrict__ Wih0,
                                               const float* __restrict__ Whh0) {
    extern __shared__ float smem[];
    float* s_x  = smem;                    /* [32][XPAD]  */
    float* s_p  = s_x + 32 * XPAD;         /* [2][16][32] */
    float* s_rm = s_p + 2 * 16 * 32;       /* [8][32]     */
    float* s_rs = s_rm + 8 * 32;
    int*   s_ri = (int*)(s_rs + 8 * 32);
    int*   s_tok = s_ri + 8 * 32;          /* [32]        */

    int tid = threadIdx.x, blk = blockIdx.x;
    int prev = t & 1, nxt = prev ^ 1;

    if (t > 0) {
        int b = tid & 31, g = tid >> 5;
        float m = -3.0e38f, ssum = 0.0f;
        int mi = 0x7fffffff;
        for (int p = g; p < NB; p += 8) {
            float pm = g_pmax[p * 32 + b];
            float ps = g_psum[p * 32 + b];
            int   pi = g_pidx[p * 32 + b];
            if (pm > m || (pm == m && pi < mi)) {
                ssum = ssum * expf(m - pm) + ps; m = pm; mi = pi;
            } else {
                ssum += ps * expf(pm - m);
            }
        }
        s_rm[g * 32 + b] = m; s_rs[g * 32 + b] = ssum; s_ri[g * 32 + b] = mi;
        __syncthreads();
        if (tid < 32) {
            float m2 = s_rm[tid], s2 = s_rs[tid];
            int i2 = s_ri[tid];
            for (int g2 = 1; g2 < 8; g2++) {
                float pm = s_rm[g2 * 32 + tid];
                float ps = s_rs[g2 * 32 + tid];
                int   pi = s_ri[g2 * 32 + tid];
                if (pm > m2 || (pm == m2 && pi < i2)) {
                    s2 = s2 * expf(m2 - pm) + ps; m2 = pm; i2 = pi;
                } else {
                    s2 += ps * expf(pm - m2);
                }
            }
            s_tok[tid] = i2;
            if (blk == 0) g_lse[(t - 1) * 32 + tid] = m2 + logf(s2);
        }
    } else {
        if (tid < 32) s_tok[tid] = START_INDEX;
        __syncthreads();                   /* match sync count of t>0 path */
    }
    __syncthreads();

    /* gather x = emb[tok[b]] into smem (b-major, padded) */
    for (int i = tid; i < 32 * 128; i += 256) {
        int b = i >> 7, q = i & 127;
        *(float4*)(s_x + b * XPAD + 4 * q) =
            *(const float4*)(emb + (size_t)s_tok[b] * 512 + 4 * q);
    }
    __syncthreads();

    int w = tid >> 5, lane = tid & 31;
    int rq = w >> 1, kh = w & 1;
    int j0 = blk * 4;
    float acc[4] = {0.f, 0.f, 0.f, 0.f};

    /* phase A: W_ih_l0[:, :512] @ emb(tok) */
    {
        const float* wbase = Wih0 + (size_t)(rq * 512 + j0) * 1024;
        const float4* xp = (const float4*)(s_x + lane * XPAD);
        for (int q = kh * 64; q < kh * 64 + 64; q++) {
            float4 xv = xp[q];
#pragma unroll
            for (int j = 0; j < 4; j++) {
                float4 a = *(const float4*)(wbase + (size_t)j * 1024 + 4 * q);
                acc[j] += a.x * xv.x + a.y * xv.y + a.z * xv.z + a.w * xv.w;
            }
        }
    }
    __syncthreads();
    /* load h0_prev */
    for (int i = tid; i < 32 * 128; i += 256) {
        int b = i >> 7, q = i & 127;
        *(float4*)(s_x + b * XPAD + 4 * q) =
            *(const float4*)(&g_h0[prev][b * 512 + 4 * q]);
    }
    __syncthreads();
    /* phase B: W_hh_l0 @ h0_prev */
    {
        const float* wbase = Whh0 + (size_t)(rq * 512 + j0) * 512;
        const float4* xp = (const float4*)(s_x + lane * XPAD);
        for (int q = kh * 64; q < kh * 64 + 64; q++) {
            float4 xv = xp[q];
#pragma unroll
            for (int j = 0; j < 4; j++) {
                float4 a = *(const float4*)(wbase + (size_t)j * 512 + 4 * q);
                acc[j] += a.x * xv.x + a.y * xv.y + a.z * xv.z + a.w * xv.w;
            }
        }
    }
#pragma unroll
    for (int j = 0; j < 4; j++)
        s_p[(kh * 16 + rq * 4 + j) * 32 + lane] = acc[j];
    __syncthreads();

    if (tid < 128) {
        int jl = tid >> 5, b = tid & 31;
        int jg = j0 + jl;
        float gi = s_p[(0 * 4 + jl) * 32 + b] + s_p[(16 + 0 * 4 + jl) * 32 + b] + g_pre0[(0 * 512 + jg) * 32 + b];
        float gf = s_p[(1 * 4 + jl) * 32 + b] + s_p[(16 + 1 * 4 + jl) * 32 + b] + g_pre0[(1 * 512 + jg) * 32 + b];
        float gg = s_p[(2 * 4 + jl) * 32 + b] + s_p[(16 + 2 * 4 + jl) * 32 + b] + g_pre0[(2 * 512 + jg) * 32 + b];
        float go = s_p[(3 * 4 + jl) * 32 + b] + s_p[(16 + 3 * 4 + jl) * 32 + b] + g_pre0[(3 * 512 + jg) * 32 + b];
        float c  = g_c0[b * 512 + jg];
        float cn = sigf(gf) * c + sigf(gi) * tanhf(gg);
        float hn = sigf(go) * tanhf(cn);
        g_c0[b * 512 + jg] = cn;
        g_h0[nxt][b * 512 + jg] = hn;
    }
}

/* ---------------------------------------------------------------------------
 * k_lstm1: layer-1 LSTM. x = h0[nxt] (just produced), h = h1[prev].
 * ------------------------------------------------------------------------- */
__global__ __launch_bounds__(256) void k_lstm1(int t,
                                               const float* __restrict__ Wih1,
                                               const float* __restrict__ Whh1,
                                               const float* __restrict__ bih1,
                                               const float* __restrict__ bhh1) {
    extern __shared__ float smem[];
    float* s_x = smem;                     /* [32][XPAD]  */
    float* s_p = s_x + 32 * XPAD;          /* [2][16][32] */
    int tid = threadIdx.x, blk = blockIdx.x;
    int prev = t & 1, nxt = prev ^ 1;

    for (int i = tid; i < 32 * 128; i += 256) {
        int b = i >> 7, q = i & 127;
        *(float4*)(s_x + b * XPAD + 4 * q) =
            *(const float4*)(&g_h0[nxt][b * 512 + 4 * q]);
    }
    __syncthreads();

    int w = tid >> 5, lane = tid & 31;
    int rq = w >> 1, kh = w & 1;
    int j0 = blk * 4;
    float acc[4] = {0.f, 0.f, 0.f, 0.f};

    {
        const float* wbase = Wih1 + (size_t)(rq * 512 + j0) * 512;
        const float4* xp = (const float4*)(s_x + lane * XPAD);
        for (int q = kh * 64; q < kh * 64 + 64; q++) {
            float4 xv = xp[q];
#pragma unroll
            for (int j = 0; j < 4; j++) {
                float4 a = *(const float4*)(wbase + (size_t)j * 512 + 4 * q);
                acc[j] += a.x * xv.x + a.y * xv.y + a.z * xv.z + a.w * xv.w;
            }
        }
    }
    __syncthreads();
    for (int i = tid; i < 32 * 128; i += 256) {
        int b = i >> 7, q = i & 127;
        *(float4*)(s_x + b * XPAD + 4 * q) =
            *(const float4*)(&g_h1[prev][b * 512 + 4 * q]);
    }
    __syncthreads();
    {
        const float* wbase = Whh1 + (size_t)(rq * 512 + j0) * 512;
        const float4* xp = (const float4*)(s_x + lane * XPAD);
        for (int q = kh * 64; q < kh * 64 + 64; q++) {
            float4 xv = xp[q];
#pragma unroll
            for (int j = 0; j < 4; j++) {
                float4 a = *(const float4*)(wbase + (size_t)j * 512 + 4 * q);
                acc[j] += a.x * xv.x + a.y * xv.y + a.z * xv.z + a.w * xv.w;
            }
        }
    }
#pragma unroll
    for (int j = 0; j < 4; j++)
        s_p[(kh * 16 + rq * 4 + j) * 32 + lane] = acc[j];
    __syncthreads();

    if (tid < 128) {
        int jl = tid >> 5, b = tid & 31;
        int jg = j0 + jl;
        int r0 = 0 * 512 + jg, r1 = 1 * 512 + jg, r2 = 2 * 512 + jg, r3 = 3 * 512 + jg;
        float gi = s_p[(0 * 4 + jl) * 32 + b] + s_p[(16 + 0 * 4 + jl) * 32 + b] + bih1[r0] + bhh1[r0];
        float gf = s_p[(1 * 4 + jl) * 32 + b] + s_p[(16 + 1 * 4 + jl) * 32 + b] + bih1[r1] + bhh1[r1];
        float gg = s_p[(2 * 4 + jl) * 32 + b] + s_p[(16 + 2 * 4 + jl) * 32 + b] + bih1[r2] + bhh1[r2];
        float go = s_p[(3 * 4 + jl) * 32 + b] + s_p[(16 + 3 * 4 + jl) * 32 + b] + bih1[r3] + bhh1[r3];
        float c  = g_c1[b * 512 + jg];
        float cn = sigf(gf) * c + sigf(gi) * tanhf(gg);
        float hn = sigf(go) * tanhf(cn);
        g_c1[b * 512 + jg] = cn;
        g_h1[nxt][b * 512 + jg] = hn;
    }
}

/* ---------------------------------------------------------------------------
 * k_logits: 250 blocks x 256 thr. Block = 128 vocab rows x 32 batches.
 * Thread tile 4v x 4b (v strided by 32, b strided by 8 -> conflict-free LDS).
 * Writes raw logits to out[b][t][:] and per-block (max, argmax, sumexp).
 * ------------------------------------------------------------------------- */
__global__ __launch_bounds__(256, 2) void k_logits(int t,
                                                   const float* __restrict__ Wout,
                                                   const float* __restrict__ bout,
                                                   float* __restrict__ out) {
    extern __shared__ float smem[];
    float* s_h  = smem;                    /* [32][XPAD] */
    float* s_rm = s_h + 32 * XPAD;         /* [32][32]   */
    float* s_rs = s_rm + 32 * 32;
    int*   s_ri = (int*)(s_rs + 32 * 32);
    int tid = threadIdx.x, blk = blockIdx.x;
    int nxt = (t & 1) ^ 1;

    for (int i = tid; i < 32 * 128; i += 256) {
        int b = i >> 7, q = i & 127;
        *(float4*)(s_h + b * XPAD + 4 * q) =
            *(const float4*)(&g_h1[nxt][b * 512 + 4 * q]);
    }
    __syncthreads();

    int vg = tid >> 3, bg = tid & 7;
    int vb = blk * VB;
    float accA[4][4], accB[4][4];
#pragma unroll
    for (int j = 0; j < 4; j++)
#pragma unroll
        for (int i = 0; i < 4; i++) { accA[j][i] = 0.f; accB[j][i] = 0.f; }

    const float* wr = Wout + (size_t)(vb + vg) * 512;
    for (int q = 0; q < 128; q++) {
        float4 hv[4], wv[4];
#pragma unroll
        for (int i = 0; i < 4; i++)
            hv[i] = *(const float4*)(s_h + (bg + 8 * i) * XPAD + 4 * q);
#pragma unroll
        for (int j = 0; j < 4; j++)
            wv[j] = *(const float4*)(wr + (size_t)j * 32 * 512 + 4 * q);
#pragma unroll
        for (int j = 0; j < 4; j++)
#pragma unroll
            for (int i = 0; i < 4; i++) {
                accA[j][i] += wv[j].x * hv[i].x + wv[j].z * hv[i].z;
                accB[j][i] += wv[j].y * hv[i].y + wv[j].w * hv[i].w;
            }
    }

    float bj[4];
#pragma unroll
    for (int j = 0; j < 4; j++) bj[j] = bout[vb + vg + 32 * j];

#pragma unroll
    for (int i = 0; i < 4; i++) {
        int b = bg + 8 * i;
        float l4[4];
        float m = -3.0e38f; int mi = 0;
#pragma unroll
        for (int j = 0; j < 4; j++) {
            float l = (accA[j][i] + accB[j][i]) + bj[j];
            l4[j] = l;
            int v = vb + vg + 32 * j;
            if (l > m) { m = l; mi = v; }     /* ascending v -> first-index ties */
            out[(size_t)b * ((size_t)T * V) + (size_t)t * V + v] = l;
        }
        float s = 0.f;
#pragma unroll
        for (int j = 0; j < 4; j++) s += expf(l4[j] - m);
        s_rm[vg * 32 + b] = m; s_rs[vg * 32 + b] = s; s_ri[vg * 32 + b] = mi;
    }
    __syncthreads();

    if (tid < 32) {
        int b = tid;
        float m = s_rm[b], s = s_rs[b];
        int mi = s_ri[b];
        for (int g = 1; g < 32; g++) {
            float pm = s_rm[g * 32 + b], ps = s_rs[g * 32 + b];
            int   pi = s_ri[g * 32 + b];
            if (pm > m || (pm == m && pi < mi)) { s = s * expf(m - pm) + ps; m = pm; mi = pi; }
            else                                { s += ps * expf(pm - m); }
        }
        g_pmax[blk * 32 + b] = m;
        g_psum[blk * 32 + b] = s;
        g_pidx[blk * 32 + b] = mi;
    }
}

/* final-step LSE (no token needed) */
__global__ void k_finlse() {
    __shared__ float s_rm[8 * 32], s_rs[8 * 32];
    __shared__ int   s_ri[8 * 32];
    int tid = threadIdx.x;
    int b = tid & 31, g = tid >> 5;
    float m = -3.0e38f, ssum = 0.0f;
    int mi = 0x7fffffff;
    for (int p = g; p < NB; p += 8) {
        float pm = g_pmax[p * 32 + b], ps = g_psum[p * 32 + b];
        int   pi = g_pidx[p * 32 + b];
        if (pm > m || (pm == m && pi < mi)) { ssum = ssum * expf(m - pm) + ps; m = pm; mi = pi; }
        else                                { ssum += ps * expf(pm - m); }
    }
    s_rm[g * 32 + b] = m; s_rs[g * 32 + b] = ssum; s_ri[g * 32 + b] = mi;
    __syncthreads();
    if (tid < 32) {
        float m2 = s_rm[tid], s2 = s_rs[tid];
        int i2 = s_ri[tid];
        for (int g2 = 1; g2 < 8; g2++) {
            float pm = s_rm[g2 * 32 + tid], ps = s_rs[g2 * 32 + tid];
            int   pi = s_ri[g2 * 32 + tid];
            if (pm > m2 || (pm == m2 && pi < i2)) { s2 = s2 * expf(m2 - pm) + ps; m2 = pm; i2 = pi; }
            else                                  { s2 += ps * expf(pm - m2); }
        }
        g_lse[(T - 1) * 32 + tid] = m2 + logf(s2);
    }
}

/* out[b][t][v] -= lse[t][b]; grid covers exactly B*T*V/4 float4s */
__global__ __launch_bounds__(256) void k_norm(float* __restrict__ out) {
    int i4 = blockIdx.x * 256 + threadIdx.x;     /* < 16,384,000 */
    int flat = i4 * 4;                           /* < 65,536,000 fits int */
    int b   = flat / (T * V);
    int rem = flat - b * (T * V);
    int tt  = rem / V;
    float l = g_lse[tt * 32 + b];
    float4* p = (float4*)out + i4;
    float4 v = *p;
    v.x -= l; v.y -= l; v.z -= l; v.w -= l;
    *p = v;
}

/* -------------------------------- launch ---------------------------------- */
#define SM_PRE  (32 * XPAD * 4)                                    /* 66048 */
#define SM_L0   ((32 * XPAD + 2 * 16 * 32 + 3 * 8 * 32 + 32) * 4)  /* 73344 */
#define SM_L1   ((32 * XPAD + 2 * 16 * 32) * 4)                    /* 70144 */
#define SM_LOG  ((32 * XPAD + 3 * 32 * 32) * 4)                    /* 78336 */

extern "C" void kernel_launch(void* const* d_in, const int* in_sizes, int n_in,
                              void* d_out, int out_size) {
    const float* ctx  = (const float*)d_in[0];
    const float* emb  = (const float*)d_in[1];
    const float* Wih0 = (const float*)d_in[2];
    const float* Whh0 = (const float*)d_in[3];
    const float* bih0 = (const float*)d_in[4];
    const float* bhh0 = (const float*)d_in[5];
    const float* Wih1 = (const float*)d_in[6];
    const float* Whh1 = (const float*)d_in[7];
    const float* bih1 = (const float*)d_in[8];
    const float* bhh1 = (const float*)d_in[9];
    const float* Wout = (const float*)d_in[10];
    const float* bout = (const float*)d_in[11];
    float* out = (float*)d_out;

    /* host-side attribute calls: not stream ops, safe under capture */
    cudaFuncSetAttribute(k_pre,    cudaFuncAttributeMaxDynamicSharedMemorySize, SM_PRE);
    cudaFuncSetAttribute(k_lstm0,  cudaFuncAttributeMaxDynamicSharedMemorySize, SM_L0);
    cudaFuncSetAttribute(k_lstm1,  cudaFuncAttributeMaxDynamicSharedMemorySize, SM_L1);
    cudaFuncSetAttribute(k_logits, cudaFuncAttributeMaxDynamicSharedMemorySize, SM_LOG);

    k_pre<<<264, 256, SM_PRE>>>(ctx, Wih0, bih0, bhh0);
    for (int t = 0; t < T; t++) {
        k_lstm0<<<128, 256, SM_L0>>>(t, emb, Wih0, Whh0);
        k_lstm1<<<128, 256, SM_L1>>>(t, Wih1, Whh1, bih1, bhh1);
        k_logits<<<250, 256, SM_LOG>>>(t, Wout, bout, out);
    }
    k_finlse<<<1, 256>>>();
    k_norm<<<64000, 256>>>(out);
}

// round 7
// speedup vs baseline: 1.1798x; 1.1798x over previous
#include <cuda_runtime.h>
#include <math.h>
#include <stddef.h>

#define B 32
#define H 512
#define V 32000
#define T 64
#define VB 128
#define NB 250            /* V / VB */
#define START_INDEX 1
#define XPAD 516          /* float pad: conflict-free 16B smem reads, lane = batch */

typedef unsigned long long u64;

/* ------------------------- persistent device scratch ---------------------- */
__device__ float g_h0[2][B * H];
__device__ float g_c0[B * H];
__device__ float g_h1[2][B * H];
__device__ float g_c1[B * H];
__device__ float g_pre0[2048 * B];    /* ctx part of layer0 gates + b_ih + b_hh */
__device__ float g_pmax[NB * B];
__device__ float g_psum[NB * B];
__device__ int   g_pidx[NB * B];
__device__ float g_lse[T * B];

__device__ __forceinline__ float sigf(float x) { return 1.0f / (1.0f + expf(-x)); }

/* packed fp32x2 FMA: d.lo += a.lo*b.lo ; d.hi += a.hi*b.hi */
__device__ __forceinline__ void fma2(u64& d, u64 a, u64 b) {
    asm("fma.rn.f32x2 %0, %1, %2, %0;" : "+l"(d) : "l"(a), "l"(b));
}
union F2U { u64 u; float2 f; };
__device__ __forceinline__ float f2sum(u64 v) { F2U t; t.u = v; return t.f.x + t.f.y; }

/* ---------------------------------------------------------------------------
 * k_pre: blocks [0,256): pre0[r][b] = W_ih_l0[r][512:] . ctx[b] + b_ih + b_hh
 *        blocks [256,264): zero all states.
 * ------------------------------------------------------------------------- */
__global__ __launch_bounds__(256) void k_pre(const float* __restrict__ ctx,
                                             const float* __restrict__ Wih0,
                                             const float* __restrict__ bih0,
                                             const float* __restrict__ bhh0) {
    int blk = blockIdx.x, tid = threadIdx.x;
    if (blk >= 256) {
        int g = (blk - 256) * 256 + tid;          /* 2048 threads total */
        for (int i = g; i < B * H; i += 2048) {
            g_h0[0][i] = 0.0f; g_h0[1][i] = 0.0f; g_c0[i] = 0.0f;
            g_h1[0][i] = 0.0f; g_h1[1][i] = 0.0f; g_c1[i] = 0.0f;
        }
        return;
    }
    extern __shared__ float smem[];
    float* s_x = smem;                            /* [32][XPAD] */
    for (int i = tid; i < B * 512; i += 256) {
        int b = i >> 9, k = i & 511;
        s_x[b * XPAD + k] = ctx[i];
    }
    __syncthreads();
    int w = tid >> 5, lane = tid & 31;
    int r = blk * 8 + w;
    const ulonglong2* wp = (const ulonglong2*)(Wih0 + (size_t)r * 1024 + 512);
    const ulonglong2* xp = (const ulonglong2*)(s_x + lane * XPAD);
    u64 acc = 0;
#pragma unroll 4
    for (int q = 0; q < 128; q++) {
        ulonglong2 a = wp[q], x = xp[q];
        fma2(acc, a.x, x.x);
        fma2(acc, a.y, x.y);
    }
    g_pre0[r * 32 + lane] = f2sum(acc) + bih0[r] + bhh0[r];
}

/* ---------------------------------------------------------------------------
 * k_lstm0: prologue pass1 (all blocks) = argmax/idx of step t-1 partials (no
 * expf). Block 0 additionally computes lse[t-1] (pass2, independent expfs).
 * Then layer-0 LSTM for 4 hidden units. Grid 128 x 256.
 * Warp w: gate rq = w>>1, k-half kh = w&1, 4 rows.
 * ------------------------------------------------------------------------- */
__global__ __launch_bounds__(256) void k_lstm0(int t,
                                               const float* __restrict__ emb,
                                               const float* __restrict__ Wih0,
                                               const float* __restrict__ Whh0) {
    extern __shared__ float smem[];
    float* s_xa = smem;                    /* [32][XPAD] emb(tok)   */
    float* s_xb = s_xa + 32 * XPAD;        /* [32][XPAD] h0 prev    */
    float* s_p  = s_xb + 32 * XPAD;        /* [2][16][32]           */
    float* s_rm = s_p + 2 * 16 * 32;       /* [8][32]               */
    int*   s_ri = (int*)(s_rm + 8 * 32);   /* [8][32]               */
    float* s_rs = (float*)(s_ri + 8 * 32); /* [8][32]               */
    int*   s_tok = (int*)(s_rs + 8 * 32);  /* [32]                  */
    float* s_fm  = (float*)(s_tok + 32);   /* [32]                  */

    int tid = threadIdx.x, blk = blockIdx.x;
    int prev = t & 1, nxt = prev ^ 1;

    /* --- pass 1: max + first-index argmax (no expf in the chain) --- */
    if (t > 0) {
        int b = tid & 31, g = tid >> 5;
        float m = -3.0e38f; int mi = 0x7fffffff;
        for (int p = g; p < NB; p += 8) {
            float pm = g_pmax[p * 32 + b];
            int   pi = g_pidx[p * 32 + b];
            if (pm > m || (pm == m && pi < mi)) { m = pm; mi = pi; }
        }
        s_rm[g * 32 + b] = m; s_ri[g * 32 + b] = mi;
    }
    __syncthreads();
    if (tid < 32) {
        if (t > 0) {
            float m = s_rm[tid]; int mi = s_ri[tid];
            for (int g = 1; g < 8; g++) {
                float pm = s_rm[g * 32 + tid];
                int   pi = s_ri[g * 32 + tid];
                if (pm > m || (pm == m && pi < mi)) { m = pm; mi = pi; }
            }
            s_tok[tid] = mi; s_fm[tid] = m;
        } else {
            s_tok[tid] = START_INDEX;
        }
    }
    __syncthreads();

    /* --- pass 2 (block 0 only): lse[t-1]; expfs are independent --- */
    if (t > 0 && blk == 0) {
        int b = tid & 31, g = tid >> 5;
        float mb = s_fm[b];
        float s = 0.0f;
        for (int p = g; p < NB; p += 8)
            s += g_psum[p * 32 + b] * expf(g_pmax[p * 32 + b] - mb);
        s_rs[g * 32 + b] = s;
        __syncthreads();
        if (tid < 32) {
            float s2 = 0.0f;
            for (int g2 = 0; g2 < 8; g2++) s2 += s_rs[g2 * 32 + tid];
            g_lse[(t - 1) * 32 + tid] = s_fm[tid] + logf(s2);
        }
    }

    /* --- load both x operands up front, one barrier --- */
    for (int i = tid; i < 32 * 128; i += 256) {
        int b = i >> 7, q = i & 127;
        *(float4*)(s_xa + b * XPAD + 4 * q) =
            *(const float4*)(emb + (size_t)s_tok[b] * 512 + 4 * q);
        *(float4*)(s_xb + b * XPAD + 4 * q) =
            *(const float4*)(&g_h0[prev][b * 512 + 4 * q]);
    }
    __syncthreads();

    int w = tid >> 5, lane = tid & 31;
    int rq = w >> 1, kh = w & 1;
    int j0 = blk * 4;
    u64 acc[4] = {0, 0, 0, 0};

    /* phase A: W_ih_l0[:, :512] @ emb(tok)   (row stride 1024 fl = 256 u2) */
    {
        const ulonglong2* xp = (const ulonglong2*)(s_xa + lane * XPAD);
        const ulonglong2* wp = (const ulonglong2*)(Wih0 + (size_t)(rq * 512 + j0) * 1024);
#pragma unroll 2
        for (int q = kh * 64; q < kh * 64 + 64; q++) {
            ulonglong2 xv = xp[q];
            ulonglong2 w0 = wp[q], w1 = wp[256 + q], w2 = wp[512 + q], w3 = wp[768 + q];
            fma2(acc[0], w0.x, xv.x); fma2(acc[0], w0.y, xv.y);
            fma2(acc[1], w1.x, xv.x); fma2(acc[1], w1.y, xv.y);
            fma2(acc[2], w2.x, xv.x); fma2(acc[2], w2.y, xv.y);
            fma2(acc[3], w3.x, xv.x); fma2(acc[3], w3.y, xv.y);
        }
    }
    /* phase B: W_hh_l0 @ h0_prev   (row stride 512 fl = 128 u2) */
    {
        const ulonglong2* xp = (const ulonglong2*)(s_xb + lane * XPAD);
        const ulonglong2* wp = (const ulonglong2*)(Whh0 + (size_t)(rq * 512 + j0) * 512);
#pragma unroll 2
        for (int q = kh * 64; q < kh * 64 + 64; q++) {
            ulonglong2 xv = xp[q];
            ulonglong2 w0 = wp[q], w1 = wp[128 + q], w2 = wp[256 + q], w3 = wp[384 + q];
            fma2(acc[0], w0.x, xv.x); fma2(acc[0], w0.y, xv.y);
            fma2(acc[1], w1.x, xv.x); fma2(acc[1], w1.y, xv.y);
            fma2(acc[2], w2.x, xv.x); fma2(acc[2], w2.y, xv.y);
            fma2(acc[3], w3.x, xv.x); fma2(acc[3], w3.y, xv.y);
        }
    }
#pragma unroll
    for (int j = 0; j < 4; j++)
        s_p[(kh * 16 + rq * 4 + j) * 32 + lane] = f2sum(acc[j]);
    __syncthreads();

    if (tid < 128) {
        int jl = tid >> 5, b = tid & 31;
        int jg = j0 + jl;
        float gi = s_p[(0 * 4 + jl) * 32 + b] + s_p[(16 + 0 * 4 + jl) * 32 + b] + g_pre0[(0 * 512 + jg) * 32 + b];
        float gf = s_p[(1 * 4 + jl) * 32 + b] + s_p[(16 + 1 * 4 + jl) * 32 + b] + g_pre0[(1 * 512 + jg) * 32 + b];
        float gg = s_p[(2 * 4 + jl) * 32 + b] + s_p[(16 + 2 * 4 + jl) * 32 + b] + g_pre0[(2 * 512 + jg) * 32 + b];
        float go = s_p[(3 * 4 + jl) * 32 + b] + s_p[(16 + 3 * 4 + jl) * 32 + b] + g_pre0[(3 * 512 + jg) * 32 + b];
        float c  = g_c0[b * 512 + jg];
        float cn = sigf(gf) * c + sigf(gi) * tanhf(gg);
        float hn = sigf(go) * tanhf(cn);
        g_c0[b * 512 + jg] = cn;
        g_h0[nxt][b * 512 + jg] = hn;
    }
}

/* ---------------------------------------------------------------------------
 * k_lstm1: layer-1 LSTM. x = h0[nxt] (just produced), h = h1[prev].
 * ------------------------------------------------------------------------- */
__global__ __launch_bounds__(256) void k_lstm1(int t,
                                               const float* __restrict__ Wih1,
                                               const float* __restrict__ Whh1,
                                               const float* __restrict__ bih1,
                                               const float* __restrict__ bhh1) {
    extern __shared__ float smem[];
    float* s_xa = smem;                    /* [32][XPAD] h0 new  */
    float* s_xb = s_xa + 32 * XPAD;        /* [32][XPAD] h1 prev */
    float* s_p  = s_xb + 32 * XPAD;        /* [2][16][32]        */
    int tid = threadIdx.x, blk = blockIdx.x;
    int prev = t & 1, nxt = prev ^ 1;

    for (int i = tid; i < 32 * 128; i += 256) {
        int b = i >> 7, q = i & 127;
        *(float4*)(s_xa + b * XPAD + 4 * q) =
            *(const float4*)(&g_h0[nxt][b * 512 + 4 * q]);
        *(float4*)(s_xb + b * XPAD + 4 * q) =
            *(const float4*)(&g_h1[prev][b * 512 + 4 * q]);
    }
    __syncthreads();

    int w = tid >> 5, lane = tid & 31;
    int rq = w >> 1, kh = w & 1;
    int j0 = blk * 4;
    u64 acc[4] = {0, 0, 0, 0};

    {
        const ulonglong2* xp = (const ulonglong2*)(s_xa + lane * XPAD);
        const ulonglong2* wp = (const ulonglong2*)(Wih1 + (size_t)(rq * 512 + j0) * 512);
#pragma unroll 2
        for (int q = kh * 64; q < kh * 64 + 64; q++) {
            ulonglong2 xv = xp[q];
            ulonglong2 w0 = wp[q], w1 = wp[128 + q], w2 = wp[256 + q], w3 = wp[384 + q];
            fma2(acc[0], w0.x, xv.x); fma2(acc[0], w0.y, xv.y);
            fma2(acc[1], w1.x, xv.x); fma2(acc[1], w1.y, xv.y);
            fma2(acc[2], w2.x, xv.x); fma2(acc[2], w2.y, xv.y);
            fma2(acc[3], w3.x, xv.x); fma2(acc[3], w3.y, xv.y);
        }
    }
    {
        const ulonglong2* xp = (const ulonglong2*)(s_xb + lane * XPAD);
        const ulonglong2* wp = (const ulonglong2*)(Whh1 + (size_t)(rq * 512 + j0) * 512);
#pragma unroll 2
        for (int q = kh * 64; q < kh * 64 + 64; q++) {
            ulonglong2 xv = xp[q];
            ulonglong2 w0 = wp[q], w1 = wp[128 + q], w2 = wp[256 + q], w3 = wp[384 + q];
            fma2(acc[0], w0.x, xv.x); fma2(acc[0], w0.y, xv.y);
            fma2(acc[1], w1.x, xv.x); fma2(acc[1], w1.y, xv.y);
            fma2(acc[2], w2.x, xv.x); fma2(acc[2], w2.y, xv.y);
            fma2(acc[3], w3.x, xv.x); fma2(acc[3], w3.y, xv.y);
        }
    }
#pragma unroll
    for (int j = 0; j < 4; j++)
        s_p[(kh * 16 + rq * 4 + j) * 32 + lane] = f2sum(acc[j]);
    __syncthreads();

    if (tid < 128) {
        int jl = tid >> 5, b = tid & 31;
        int jg = j0 + jl;
        int r0 = 0 * 512 + jg, r1 = 1 * 512 + jg, r2 = 2 * 512 + jg, r3 = 3 * 512 + jg;
        float gi = s_p[(0 * 4 + jl) * 32 + b] + s_p[(16 + 0 * 4 + jl) * 32 + b] + bih1[r0] + bhh1[r0];
        float gf = s_p[(1 * 4 + jl) * 32 + b] + s_p[(16 + 1 * 4 + jl) * 32 + b] + bih1[r1] + bhh1[r1];
        float gg = s_p[(2 * 4 + jl) * 32 + b] + s_p[(16 + 2 * 4 + jl) * 32 + b] + bih1[r2] + bhh1[r2];
        float go = s_p[(3 * 4 + jl) * 32 + b] + s_p[(16 + 3 * 4 + jl) * 32 + b] + bih1[r3] + bhh1[r3];
        float c  = g_c1[b * 512 + jg];
        float cn = sigf(gf) * c + sigf(gi) * tanhf(gg);
        float hn = sigf(go) * tanhf(cn);
        g_c1[b * 512 + jg] = cn;
        g_h1[nxt][b * 512 + jg] = hn;
    }
}

/* ---------------------------------------------------------------------------
 * k_logits: 250 blocks x 256 thr. Block = 128 vocab rows x 32 batches.
 * Thread tile 4v x 4b; f32x2 packed FMA over consecutive-k pairs.
 * Streaming stores for `out` (protect W_out L2 residency).
 * ------------------------------------------------------------------------- */
__global__ __launch_bounds__(256, 2) void k_logits(int t,
                                                   const float* __restrict__ Wout,
                                                   const float* __restrict__ bout,
                                                   float* __restrict__ out) {
    extern __shared__ float smem[];
    float* s_h  = smem;                    /* [32][XPAD] */
    float* s_rm = s_h + 32 * XPAD;         /* [32][32]   */
    float* s_rs = s_rm + 32 * 32;
    int*   s_ri = (int*)(s_rs + 32 * 32);
    int tid = threadIdx.x, blk = blockIdx.x;
    int nxt = (t & 1) ^ 1;

    for (int i = tid; i < 32 * 128; i += 256) {
        int b = i >> 7, q = i & 127;
        *(float4*)(s_h + b * XPAD + 4 * q) =
            *(const float4*)(&g_h1[nxt][b * 512 + 4 * q]);
    }
    __syncthreads();

    int vg = tid >> 3, bg = tid & 7;
    int vb = blk * VB;
    u64 acc[4][4];
#pragma unroll
    for (int j = 0; j < 4; j++)
#pragma unroll
        for (int i = 0; i < 4; i++) acc[j][i] = 0;

    const ulonglong2* wr = (const ulonglong2*)(Wout + (size_t)(vb + vg) * 512);
    for (int q = 0; q < 128; q++) {
        ulonglong2 hv[4], wv[4];
#pragma unroll
        for (int i = 0; i < 4; i++)
            hv[i] = *(const ulonglong2*)(s_h + (bg + 8 * i) * XPAD + 4 * q);
#pragma unroll
        for (int j = 0; j < 4; j++)
            wv[j] = wr[j * 4096 + q];      /* 32 rows * 128 u2/row */
#pragma unroll
        for (int j = 0; j < 4; j++)
#pragma unroll
            for (int i = 0; i < 4; i++) {
                fma2(acc[j][i], wv[j].x, hv[i].x);
                fma2(acc[j][i], wv[j].y, hv[i].y);
            }
    }

    float bj[4];
#pragma unroll
    for (int j = 0; j < 4; j++) bj[j] = bout[vb + vg + 32 * j];

#pragma unroll
    for (int i = 0; i < 4; i++) {
        int b = bg + 8 * i;
        float l4[4];
        float m = -3.0e38f; int mi = 0;
#pragma unroll
        for (int j = 0; j < 4; j++) {
            float l = f2sum(acc[j][i]) + bj[j];
            l4[j] = l;
            int v = vb + vg + 32 * j;
            if (l > m) { m = l; mi = v; }   /* ascending v -> first-index ties */
            __stcs(&out[(size_t)b * ((size_t)T * V) + (size_t)t * V + v], l);
        }
        float s = 0.f;
#pragma unroll
        for (int j = 0; j < 4; j++) s += expf(l4[j] - m);
        s_rm[vg * 32 + b] = m; s_rs[vg * 32 + b] = s; s_ri[vg * 32 + b] = mi;
    }
    __syncthreads();

    if (tid < 32) {
        int b = tid;
        float m = s_rm[b]; int mi = s_ri[b];
        for (int g = 1; g < 32; g++) {       /* pass 1: cheap max/idx chain */
            float pm = s_rm[g * 32 + b]; int pi = s_ri[g * 32 + b];
            if (pm > m || (pm == m && pi < mi)) { m = pm; mi = pi; }
        }
        float s = 0.f;                       /* pass 2: independent expfs */
        for (int g = 0; g < 32; g++) s += s_rs[g * 32 + b] * expf(s_rm[g * 32 + b] - m);
        g_pmax[blk * 32 + b] = m;
        g_psum[blk * 32 + b] = s;
        g_pidx[blk * 32 + b] = mi;
    }
}

/* final-step LSE */
__global__ void k_finlse() {
    __shared__ float s_rm[8 * 32], s_rs[8 * 32];
    __shared__ float s_fm[32];
    int tid = threadIdx.x;
    int b = tid & 31, g = tid >> 5;
    float m = -3.0e38f;
    for (int p = g; p < NB; p += 8) m = fmaxf(m, g_pmax[p * 32 + b]);
    s_rm[g * 32 + b] = m;
    __syncthreads();
    if (tid < 32) {
        float m2 = s_rm[tid];
        for (int g2 = 1; g2 < 8; g2++) m2 = fmaxf(m2, s_rm[g2 * 32 + tid]);
        s_fm[tid] = m2;
    }
    __syncthreads();
    float mb = s_fm[b];
    float s = 0.0f;
    for (int p = g; p < NB; p += 8)
        s += g_psum[p * 32 + b] * expf(g_pmax[p * 32 + b] - mb);
    s_rs[g * 32 + b] = s;
    __syncthreads();
    if (tid < 32) {
        float s2 = 0.0f;
        for (int g2 = 0; g2 < 8; g2++) s2 += s_rs[g2 * 32 + tid];
        g_lse[(T - 1) * 32 + tid] = s_fm[tid] + logf(s2);
    }
}

/* out[b][t][v] -= lse[t][b]; streaming loads/stores */
__global__ __launch_bounds__(256) void k_norm(float* __restrict__ out) {
    int i4 = blockIdx.x * 256 + threadIdx.x;     /* < 16,384,000 */
    int flat = i4 * 4;
    int b   = flat / (T * V);
    int rem = flat - b * (T * V);
    int tt  = rem / V;
    float l = g_lse[tt * 32 + b];
    float4* p = (float4*)out + i4;
    float4 v = __ldcs(p);
    v.x -= l; v.y -= l; v.z -= l; v.w -= l;
    __stcs(p, v);
}

/* -------------------------------- launch ---------------------------------- */
#define SM_PRE  (32 * XPAD * 4)
#define SM_L0   ((2 * 32 * XPAD + 2 * 16 * 32 + 3 * 8 * 32 + 64) * 4)
#define SM_L1   ((2 * 32 * XPAD + 2 * 16 * 32) * 4)
#define SM_LOG  ((32 * XPAD + 3 * 32 * 32) * 4)

extern "C" void kernel_launch(void* const* d_in, const int* in_sizes, int n_in,
                              void* d_out, int out_size) {
    const float* ctx  = (const float*)d_in[0];
    const float* emb  = (const float*)d_in[1];
    const float* Wih0 = (const float*)d_in[2];
    const float* Whh0 = (const float*)d_in[3];
    const float* bih0 = (const float*)d_in[4];
    const float* bhh0 = (const float*)d_in[5];
    const float* Wih1 = (const float*)d_in[6];
    const float* Whh1 = (const float*)d_in[7];
    const float* bih1 = (const float*)d_in[8];
    const float* bhh1 = (const float*)d_in[9];
    const float* Wout = (const float*)d_in[10];
    const float* bout = (const float*)d_in[11];
    float* out = (float*)d_out;

    cudaFuncSetAttribute(k_pre,    cudaFuncAttributeMaxDynamicSharedMemorySize, SM_PRE);
    cudaFuncSetAttribute(k_lstm0,  cudaFuncAttributeMaxDynamicSharedMemorySize, SM_L0);
    cudaFuncSetAttribute(k_lstm1,  cudaFuncAttributeMaxDynamicSharedMemorySize, SM_L1);
    cudaFuncSetAttribute(k_logits, cudaFuncAttributeMaxDynamicSharedMemorySize, SM_LOG);

    k_pre<<<264, 256, SM_PRE>>>(ctx, Wih0, bih0, bhh0);
    for (int t = 0; t < T; t++) {
        k_lstm0<<<128, 256, SM_L0>>>(t, emb, Wih0, Whh0);
        k_lstm1<<<128, 256, SM_L1>>>(t, Wih1, Whh1, bih1, bhh1);
        k_logits<<<250, 256, SM_LOG>>>(t, Wout, bout, out);
    }
    k_finlse<<<1, 256>>>();
    k_norm<<<64000, 256>>>(out);
}